// round 15
// baseline (speedup 1.0000x reference)
#include <cuda_runtime.h>
#include <cuda_fp16.h>
#include <math.h>
#include <stdint.h>

// ---------------- problem constants ----------------
#define BB 16
#define SS 1024
#define D_IN 576
#define DM 512
#define DFF 2048
#define DHID 128
#define NKK 50
#define NL 3
#define NH 8
#define MTOT (BB*SS)   // 16384

#define WSCALE 256.f
#define WINV   0.00390625f

// ---------------- fp16 split ----------------
__device__ __forceinline__ void f16_split(float v, __half& h, __half& l) {
    h = __float2half_rn(v);
    l = __float2half_rn(v - __half2float(h));
}

// ---------------- scratch ----------------
#define OFF_WIN   0
#define OFF_QKV(l) (368640 + (l) * 983040)
#define OFF_WO(l)  (3317760 + (l) * 327680)
#define OFF_W1(l)  (4300800 + (l) * 1310720)
#define OFF_W2(l)  (8232960 + (l) * 1310720)
#define OFF_WOUT  12165120
#define OFF_WK1   12247040
#define OFF_WSUB  12267520
#define WT_TOTAL  12288000

__device__ __half g_fh  [MTOT * D_IN];
__device__ __half g_fl  [MTOT * D_IN];
__device__ float  g_x   [MTOT * DM];
__device__ __half g_xh  [MTOT * DM];
__device__ __half g_xl  [MTOT * DM];
__device__ __half g_qkvh[MTOT * 3 * DM];
__device__ __half g_qkvl[MTOT * 3 * DM];
__device__ float  g_klog[MTOT * 128];
__device__ __half g_oh  [MTOT * DM];
__device__ __half g_ol  [MTOT * DM];
__device__ float  g_proj[MTOT * DM];
__device__ __half g_ffnh[MTOT * DFF];      // reused late as hid_h
__device__ __half g_ffnl[MTOT * DFF];      // reused late as hid_l
__device__ float  g_out [MTOT * DHID];
__device__ __half g_outh[MTOT * DHID];
__device__ __half g_outl[MTOT * DHID];
__device__ float  g_mlog[MTOT * 2];
__device__ __half g_wth [WT_TOTAL];
__device__ __half g_wtl [WT_TOTAL];
__device__ float  g_bsub[128];
__device__ float  g_bqkv[3 * DM];
__device__ int    g_kidx[MTOT];
__device__ int    g_flag[MTOT];
__device__ int    g_fill[MTOT];

// ---------------- concat + split ----------------
__global__ void concat_split(const float* __restrict__ st, const float* __restrict__ ac,
                             const float* __restrict__ go) {
    int idx = blockIdx.x * blockDim.x + threadIdx.x;
    if (idx >= MTOT * D_IN) return;
    int m = idx / D_IN, c = idx % D_IN;
    float v;
    if (c < 256)      v = st[(size_t)m * 256 + c];
    else if (c < 320) v = ac[(size_t)m * 64 + (c - 256)];
    else              v = go[(size_t)m * 256 + (c - 320)];
    __half h, l;
    f16_split(v, h, l);
    g_fh[idx] = h;
    g_fl[idx] = l;
}

// ---------------- weight transpose + split + fp16 fragment-pack ----------------
__global__ void tsplit(const float* __restrict__ W, __half* __restrict__ Th,
                       __half* __restrict__ Tl, int K, int N, int realN,
                       float qscale, int qcut) {
    __shared__ float t[32][33];
    int k0 = blockIdx.y * 32, n0 = blockIdx.x * 32;
    int tx = threadIdx.x, ty = threadIdx.y;  // 32x8
    #pragma unroll
    for (int i = ty; i < 32; i += 8) {
        int n = n0 + tx;
        float scl = WSCALE * ((n < qcut) ? qscale : 1.f);
        t[i][tx] = (n < realN) ? W[(size_t)(k0 + i) * realN + n] * scl : 0.f;
    }
    __syncthreads();
    #pragma unroll
    for (int i = ty; i < 32; i += 8) {
        int n = n0 + i, k = k0 + tx;
        float v = t[tx][i];
        __half h, l;
        f16_split(v, h, l);
        int nb = n >> 7, nr = n & 127;
        int kc = k >> 5, ks = (k >> 4) & 1, p = (k & 15) >> 1;
        int tt = p & 3, reg = p >> 2;
        int slot = ((nr >> 6) << 5) + ((nr & 7) << 2) + tt;
        int u32idx = (((nr >> 5) & 1) << 3) + (((nr >> 3) & 3) << 1) + reg;
        size_t off = ((((size_t)(nb * (K >> 5) + kc)) * 2560 + ks * 1280 + slot * 20 + u32idx) << 1) + (k & 1);
        Th[off] = h;
        Tl[off] = l;
    }
}

__global__ void bias_pad(const float* __restrict__ b, float* __restrict__ bp, int realN) {
    int i = threadIdx.x;
    bp[i] = (i < realN) ? b[i] : 0.f;
}

__global__ void scale_bqkv(const float* __restrict__ b) {
    int i = blockIdx.x * 256 + threadIdx.x;
    if (i < 3 * DM) g_bqkv[i] = b[i] * ((i < DM) ? 0.125f : 1.f);
}

// ---------------- mma.sync fp16 helper ----------------
__device__ __forceinline__ void mma_f16(float* c, const uint32_t* a, const uint32_t* b) {
    asm volatile(
        "mma.sync.aligned.m16n8k16.row.col.f32.f16.f16.f32 "
        "{%0,%1,%2,%3}, {%4,%5,%6,%7}, {%8,%9}, {%0,%1,%2,%3};"
        : "+f"(c[0]), "+f"(c[1]), "+f"(c[2]), "+f"(c[3])
        : "r"(a[0]), "r"(a[1]), "r"(a[2]), "r"(a[3]), "r"(b[0]), "r"(b[1]));
}
__device__ __forceinline__ void cpa16(uint32_t dst, const void* src) {
    asm volatile("cp.async.cg.shared.global [%0], [%1], 16;" :: "r"(dst), "l"(src));
}
__device__ __forceinline__ uint32_t smem_u32(const void* p) {
    uint32_t a;
    asm("{ .reg .u64 t; cvta.to.shared.u64 t, %1; cvt.u32.u64 %0, t; }" : "=r"(a) : "l"(p));
    return a;
}

// ---------------- tensor-pipe fp16x3 GEMM: M=64 tiles, 3 CTAs/SM ----------------
#define TAu 1280
#define TBu 2560
#define STAGE_U 7680
#define TG_SMEM (2 * STAGE_U * 4)   // 61440 bytes -> 3 CTAs/SM

template<bool RELU, bool WRITE_C, bool WRITE_SPLIT>
__global__ __launch_bounds__(256, 3)
void tgemm(const __half* __restrict__ Ah, const __half* __restrict__ Al,
           const __half* __restrict__ Bph, const __half* __restrict__ Bpl,
           const float* __restrict__ bias,
           float* __restrict__ C, __half* __restrict__ Ch, __half* __restrict__ Cl,
           int N, int K) {
    extern __shared__ uint32_t smu[];
    const int tid = threadIdx.x;
    const int wid = tid >> 5, lane = tid & 31;
    const int g = lane >> 2, t = lane & 3;
    const int wm = (wid & 3) * 16;
    const int wcol = wid >> 2;
    const int n0 = blockIdx.x * 128, m0 = blockIdx.y * 64;
    const int NC = K >> 5;
    const uint32_t smb = smem_u32(smu);

    const __half* Agh = Ah + (size_t)m0 * K;
    const __half* Agl = Al + (size_t)m0 * K;
    const size_t bbase = (size_t)blockIdx.x * (K >> 5) * 5120;
    const __half* Bgh = Bph + bbase;
    const __half* Bgl = Bpl + bbase;

    const int rA = tid >> 2, fA = tid & 3;

    auto load_chunk = [&](int c, int s) {
        uint32_t st = smb + s * STAGE_U * 4;
        cpa16(st + (rA * 20 + fA * 4) * 4,        Agh + (size_t)rA * K + c * 32 + fA * 8);
        cpa16(st + (TAu + rA * 20 + fA * 4) * 4,  Agl + (size_t)rA * K + c * 32 + fA * 8);
        const __half* bh = Bgh + (size_t)c * 5120;
        const __half* bl = Bgl + (size_t)c * 5120;
        #pragma unroll
        for (int i = 0; i < 3; i++) {
            int idx = tid + i * 256;
            if (idx < 640) {
                cpa16(st + (2 * TAu + idx * 4) * 4,       bh + idx * 8);
                cpa16(st + (2 * TAu + TBu + idx * 4) * 4, bl + idx * 8);
            }
        }
        asm volatile("cp.async.commit_group;" ::: "memory");
    };

    load_chunk(0, 0);
    if (NC > 1) load_chunk(1, 1);
    else asm volatile("cp.async.commit_group;" ::: "memory");

    float acc[8][4];
    #pragma unroll
    for (int nt = 0; nt < 8; nt++)
        #pragma unroll
        for (int u = 0; u < 4; u++) acc[nt][u] = 0.f;

    for (int c = 0; c < NC; c++) {
        const int buf = c & 1;
        if (c + 1 < NC) asm volatile("cp.async.wait_group 1;" ::: "memory");
        else            asm volatile("cp.async.wait_group 0;" ::: "memory");
        __syncthreads();

        const uint32_t* As_h = smu + buf * STAGE_U;
        const uint32_t* As_l = As_h + TAu;
        const uint32_t* Bs_h = As_h + 2 * TAu;
        const uint32_t* Bs_l = Bs_h + TBu;

        #pragma unroll
        for (int ks = 0; ks < 2; ks++) {
            const int r0 = wm + g;
            const uint32_t* ph = As_h + r0 * 20 + ks * 8 + t;
            const uint32_t* pl = As_l + r0 * 20 + ks * 8 + t;
            uint32_t ah[4] = {ph[0], ph[160], ph[4], ph[164]};
            uint32_t al[4] = {pl[0], pl[160], pl[4], pl[164]};
            const uint32_t* bsh = Bs_h + ks * 1280 + (wcol * 32 + lane) * 20;
            const uint32_t* bsl = Bs_l + ks * 1280 + (wcol * 32 + lane) * 20;
            #pragma unroll
            for (int ntg = 0; ntg < 2; ntg++) {
                uint4 h0 = *(const uint4*)(bsh + ntg * 8);
                uint4 h1 = *(const uint4*)(bsh + ntg * 8 + 4);
                uint4 l0 = *(const uint4*)(bsl + ntg * 8);
                uint4 l1 = *(const uint4*)(bsl + ntg * 8 + 4);
                uint32_t bh[4][2] = {{h0.x, h0.y}, {h0.z, h0.w}, {h1.x, h1.y}, {h1.z, h1.w}};
                uint32_t bl[4][2] = {{l0.x, l0.y}, {l0.z, l0.w}, {l1.x, l1.y}, {l1.z, l1.w}};
                #pragma unroll
                for (int nt = 0; nt < 4; nt++) {
                    mma_f16(acc[ntg * 4 + nt], ah, bh[nt]);
                    mma_f16(acc[ntg * 4 + nt], ah, bl[nt]);
                    mma_f16(acc[ntg * 4 + nt], al, bh[nt]);
                }
            }
        }
        __syncthreads();
        if (c + 2 < NC) load_chunk(c + 2, buf);
    }

    const int row0 = m0 + wm + g;
    #pragma unroll
    for (int nt = 0; nt < 8; nt++) {
        int col = n0 + wcol * 64 + nt * 8 + 2 * t;
        float b0 = bias[col], b1 = bias[col + 1];
        float v00 = acc[nt][0] * WINV + b0, v01 = acc[nt][1] * WINV + b1;
        float v10 = acc[nt][2] * WINV + b0, v11 = acc[nt][3] * WINV + b1;
        if (RELU) {
            v00 = fmaxf(v00, 0.f); v01 = fmaxf(v01, 0.f);
            v10 = fmaxf(v10, 0.f); v11 = fmaxf(v11, 0.f);
        }
        size_t i0 = (size_t)row0 * N + col;
        size_t i1 = (size_t)(row0 + 8) * N + col;
        if (WRITE_C) {
            *(float2*)(C + i0) = make_float2(v00, v01);
            *(float2*)(C + i1) = make_float2(v10, v11);
        }
        if (WRITE_SPLIT) {
            __half h00, l00, h01, l01, h10, l10, h11, l11;
            f16_split(v00, h00, l00); f16_split(v01, h01, l01);
            f16_split(v10, h10, l10); f16_split(v11, h11, l11);
            *(__half2*)(Ch + i0) = __halves2half2(h00, h01);
            *(__half2*)(Cl + i0) = __halves2half2(l00, l01);
            *(__half2*)(Ch + i1) = __halves2half2(h10, h11);
            *(__half2*)(Cl + i1) = __halves2half2(l10, l11);
        }
    }
}

// ---------------- m-logit head: warp-per-row dot (N=2, K=128) ----------------
__global__ __launch_bounds__(128)
void mlogit_kernel(const float* __restrict__ A, const float* __restrict__ W,
                   const float* __restrict__ b) {
    const int wid = threadIdx.x >> 5, lane = threadIdx.x & 31;
    const int r = blockIdx.x * 4 + wid;
    float4 a = *(const float4*)(A + (size_t)r * DHID + lane * 4);
    int k = lane * 4;
    float s0 = a.x * W[k * 2]     + a.y * W[(k + 1) * 2]     + a.z * W[(k + 2) * 2]     + a.w * W[(k + 3) * 2];
    float s1 = a.x * W[k * 2 + 1] + a.y * W[(k + 1) * 2 + 1] + a.z * W[(k + 2) * 2 + 1] + a.w * W[(k + 3) * 2 + 1];
    #pragma unroll
    for (int o = 16; o > 0; o >>= 1) {
        s0 += __shfl_xor_sync(0xffffffffu, s0, o);
        s1 += __shfl_xor_sync(0xffffffffu, s1, o);
    }
    if (lane == 0) {
        g_mlog[r * 2 + 0] = s0 + b[0];
        g_mlog[r * 2 + 1] = s1 + b[1];
    }
}

// ---------------- tensor-core flash attention (fp16x3; LPT order; 3 CTAs/SM) ----------------
#define APu 36
#define ATT_SMEM_B ((8 * 64 * APu + 7 * 64) * 4)

__global__ __launch_bounds__(256, 3)
void attn_mma(const __half* __restrict__ qkvh, const __half* __restrict__ qkvl,
              __half* __restrict__ oh, __half* __restrict__ ol) {
    extern __shared__ uint32_t smA[];
    uint32_t* Qh  = smA;
    uint32_t* Ql  = Qh  + 64 * APu;
    uint32_t* Kh  = Ql  + 64 * APu;
    uint32_t* Kl  = Kh  + 64 * APu;
    uint32_t* Vth = Kl  + 64 * APu;
    uint32_t* Vtl = Vth + 64 * APu;
    uint32_t* Ph  = Vtl + 64 * APu;
    uint32_t* Pl  = Ph  + 64 * APu;
    float* sm_m     = (float*)(Pl + 64 * APu);
    float* sm_l     = sm_m + 64;
    float* sm_alpha = sm_l + 64;
    float* sm_part  = sm_alpha + 64;
    float* sm_psum  = sm_part + 128;

    const int tid = threadIdx.x;
    const int wid = tid >> 5, lane = tid & 31;
    const int g = lane >> 2, t = lane & 3;
    const int wm = (wid & 3) * 16;
    const int wn = (wid >> 2) * 32;
    const int half_ = wid >> 2;
    const int qt0 = (gridDim.x - 1 - blockIdx.x) * 64;   // LPT: biggest blocks first
    const int hh = blockIdx.y, bb = blockIdx.z;
    const size_t bbase = (size_t)bb * SS * 1536;

    {
        int r = tid >> 2, dg = tid & 3;
        size_t rowo = bbase + (size_t)(qt0 + r) * 1536 + hh * 64 + dg * 16;
        const uint32_t* qh = (const uint32_t*)(qkvh + rowo);
        const uint32_t* ql = (const uint32_t*)(qkvl + rowo);
        uint32_t* dh = Qh + r * APu + dg * 8;
        uint32_t* dl = Ql + r * APu + dg * 8;
        *(uint4*)(dh)     = *(const uint4*)(qh);
        *(uint4*)(dh + 4) = *(const uint4*)(qh + 4);
        *(uint4*)(dl)     = *(const uint4*)(ql);
        *(uint4*)(dl + 4) = *(const uint4*)(ql + 4);
    }
    if (tid < 64) { sm_m[tid] = -1e30f; sm_l[tid] = 0.f; }

    float o_[4][4];
    #pragma unroll
    for (int nt = 0; nt < 4; nt++)
        #pragma unroll
        for (int u = 0; u < 4; u++) o_[nt][u] = 0.f;

    const int ntiles = qt0 / 64 + 1;
    for (int ti = 0; ti < ntiles; ti++) {
        const int t0 = ti * 64;
        __syncthreads();

        {
            int r = tid >> 2, dg = tid & 3;
            size_t rowo = bbase + (size_t)(t0 + r) * 1536 + hh * 64 + dg * 16;
            const uint32_t* kh = (const uint32_t*)(qkvh + rowo + 512);
            const uint32_t* kl = (const uint32_t*)(qkvl + rowo + 512);
            uint32_t* dh = Kh + r * APu + dg * 8;
            uint32_t* dl = Kl + r * APu + dg * 8;
            *(uint4*)(dh)     = *(const uint4*)(kh);
            *(uint4*)(dh + 4) = *(const uint4*)(kh + 4);
            *(uint4*)(dl)     = *(const uint4*)(kl);
            *(uint4*)(dl + 4) = *(const uint4*)(kl + 4);

            const __half2* vh2 = (const __half2*)(qkvh + rowo + 1024);
            const __half2* vl2 = (const __half2*)(qkvl + rowo + 1024);
            __half* VthH = (__half*)Vth;
            __half* VtlH = (__half*)Vtl;
            int d0 = dg * 16;
            #pragma unroll
            for (int j = 0; j < 8; j++) {
                __half2 hv = vh2[j];
                __half2 lv = vl2[j];
                int d = d0 + 2 * j;
                VthH[(d)     * 2 * APu + r] = __low2half(hv);
                VthH[(d + 1) * 2 * APu + r] = __high2half(hv);
                VtlH[(d)     * 2 * APu + r] = __low2half(lv);
                VtlH[(d + 1) * 2 * APu + r] = __high2half(lv);
            }
        }
        __syncthreads();

        float c0[4][4];
        #pragma unroll
        for (int nt = 0; nt < 4; nt++)
            #pragma unroll
            for (int u = 0; u < 4; u++) c0[nt][u] = 0.f;

        #pragma unroll
        for (int kt = 0; kt < 4; kt++) {
            const int ko = kt * 8;
            const uint32_t* qph = Qh + (wm + g) * APu + ko + t;
            const uint32_t* qpl = Ql + (wm + g) * APu + ko + t;
            uint32_t ahf[4] = {qph[0], qph[8 * APu], qph[4], qph[8 * APu + 4]};
            uint32_t alf[4] = {qpl[0], qpl[8 * APu], qpl[4], qpl[8 * APu + 4]};
            #pragma unroll
            for (int nt = 0; nt < 4; nt++) {
                const uint32_t* kph = Kh + (wn + nt * 8 + g) * APu + ko;
                const uint32_t* kpl = Kl + (wn + nt * 8 + g) * APu + ko;
                uint32_t bhf[2] = {kph[t], kph[t + 4]};
                uint32_t blf[2] = {kpl[t], kpl[t + 4]};
                mma_f16(c0[nt], ahf, bhf);
                mma_f16(c0[nt], ahf, blf);
                mma_f16(c0[nt], alf, bhf);
            }
        }

        if (t0 == qt0) {
            int r0 = qt0 + wm + g, r1 = r0 + 8;
            #pragma unroll
            for (int nt = 0; nt < 4; nt++) {
                int cb = t0 + wn + nt * 8 + 2 * t;
                if (cb     > r0) c0[nt][0] = -1e30f;
                if (cb + 1 > r0) c0[nt][1] = -1e30f;
                if (cb     > r1) c0[nt][2] = -1e30f;
                if (cb + 1 > r1) c0[nt][3] = -1e30f;
            }
        }

        float m0p = -1e30f, m1p = -1e30f;
        #pragma unroll
        for (int nt = 0; nt < 4; nt++) {
            m0p = fmaxf(m0p, fmaxf(c0[nt][0], c0[nt][1]));
            m1p = fmaxf(m1p, fmaxf(c0[nt][2], c0[nt][3]));
        }
        #pragma unroll
        for (int o = 1; o <= 2; o <<= 1) {
            m0p = fmaxf(m0p, __shfl_xor_sync(0xffffffffu, m0p, o));
            m1p = fmaxf(m1p, __shfl_xor_sync(0xffffffffu, m1p, o));
        }
        if (t == 0) {
            sm_part[(wm + g) * 2 + half_] = m0p;
            sm_part[(wm + g + 8) * 2 + half_] = m1p;
        }
        __syncthreads();
        if (tid < 64) {
            float mo = sm_m[tid];
            float mn = fmaxf(mo, fmaxf(sm_part[tid * 2], sm_part[tid * 2 + 1]));
            sm_alpha[tid] = __expf(mo - mn);
            sm_m[tid] = mn;
        }
        __syncthreads();

        {
            float mn0 = sm_m[wm + g], mn1 = sm_m[wm + g + 8];
            float ps0 = 0.f, ps1 = 0.f;
            #pragma unroll
            for (int nt = 0; nt < 4; nt++) {
                int pi = ((wn + nt * 8) >> 1) + t;
                float p00 = __expf(c0[nt][0] - mn0), p01 = __expf(c0[nt][1] - mn0);
                float p10 = __expf(c0[nt][2] - mn1), p11 = __expf(c0[nt][3] - mn1);
                ps0 += p00 + p01; ps1 += p10 + p11;
                __half h00, l00, h01, l01, h10, l10, h11, l11;
                f16_split(p00, h00, l00); f16_split(p01, h01, l01);
                f16_split(p10, h10, l10); f16_split(p11, h11, l11);
                ((__half2*)Ph)[(wm + g) * APu + pi]     = __halves2half2(h00, h01);
                ((__half2*)Pl)[(wm + g) * APu + pi]     = __halves2half2(l00, l01);
                ((__half2*)Ph)[(wm + g + 8) * APu + pi] = __halves2half2(h10, h11);
                ((__half2*)Pl)[(wm + g + 8) * APu + pi] = __halves2half2(l10, l11);
            }
            #pragma unroll
            for (int o = 1; o <= 2; o <<= 1) {
                ps0 += __shfl_xor_sync(0xffffffffu, ps0, o);
                ps1 += __shfl_xor_sync(0xffffffffu, ps1, o);
            }
            if (t == 0) {
                sm_psum[(wm + g) * 2 + half_] = ps0;
                sm_psum[(wm + g + 8) * 2 + half_] = ps1;
            }
        }
        __syncthreads();
        if (tid < 64)
            sm_l[tid] = sm_l[tid] * sm_alpha[tid] + sm_psum[tid * 2] + sm_psum[tid * 2 + 1];

        {
            float al0 = sm_alpha[wm + g], al1 = sm_alpha[wm + g + 8];
            #pragma unroll
            for (int nt = 0; nt < 4; nt++) {
                o_[nt][0] *= al0; o_[nt][1] *= al0;
                o_[nt][2] *= al1; o_[nt][3] *= al1;
            }
            #pragma unroll
            for (int kt = 0; kt < 4; kt++) {
                const int ko = kt * 8;
                const uint32_t* pph = Ph + (wm + g) * APu + ko + t;
                const uint32_t* ppl = Pl + (wm + g) * APu + ko + t;
                uint32_t ahf[4] = {pph[0], pph[8 * APu], pph[4], pph[8 * APu + 4]};
                uint32_t alf[4] = {ppl[0], ppl[8 * APu], ppl[4], ppl[8 * APu + 4]};
                #pragma unroll
                for (int nt = 0; nt < 4; nt++) {
                    const uint32_t* vph = Vth + (wn + nt * 8 + g) * APu + ko;
                    const uint32_t* vpl = Vtl + (wn + nt * 8 + g) * APu + ko;
                    uint32_t bhf[2] = {vph[t], vph[t + 4]};
                    uint32_t blf[2] = {vpl[t], vpl[t + 4]};
                    mma_f16(o_[nt], ahf, bhf);
                    mma_f16(o_[nt], ahf, blf);
                    mma_f16(o_[nt], alf, bhf);
                }
            }
        }
    }

    __syncthreads();
    float il0 = 1.f / sm_l[wm + g], il1 = 1.f / sm_l[wm + g + 8];
    int r0 = bb * SS + qt0 + wm + g;
    #pragma unroll
    for (int nt = 0; nt < 4; nt++) {
        int co = hh * 64 + wn + nt * 8 + 2 * t;
        float v00 = o_[nt][0] * il0, v01 = o_[nt][1] * il0;
        float v10 = o_[nt][2] * il1, v11 = o_[nt][3] * il1;
        __half h00, l00, h01, l01, h10, l10, h11, l11;
        f16_split(v00, h00, l00); f16_split(v01, h01, l01);
        f16_split(v10, h10, l10); f16_split(v11, h11, l11);
        size_t i0 = (size_t)r0 * DM + co;
        size_t i1 = (size_t)(r0 + 8) * DM + co;
        *(__half2*)(oh + i0) = __halves2half2(h00, h01);
        *(__half2*)(ol + i0) = __halves2half2(l00, l01);
        *(__half2*)(oh + i1) = __halves2half2(h10, h11);
        *(__half2*)(ol + i1) = __halves2half2(l10, l11);
    }
}

// ---------------- residual + layernorm: warp-per-row ----------------
__global__ __launch_bounds__(128)
void ln_kernel(const float* __restrict__ x, const float* __restrict__ h,
               const float* __restrict__ g, const float* __restrict__ b,
               float* __restrict__ out, __half* __restrict__ oh, __half* __restrict__ ol) {
    const int wid = threadIdx.x >> 5, lane = threadIdx.x & 31;
    const int row = blockIdx.x * 4 + wid;
    const float* xr = x + (size_t)row * DM;
    const float* hr = h + (size_t)row * DM;

    float v[16];
    float s = 0.f;
    #pragma unroll
    for (int i = 0; i < 4; i++) {
        float4 xv = *(const float4*)(xr + i * 128 + lane * 4);
        float4 hv = *(const float4*)(hr + i * 128 + lane * 4);
        v[i*4+0] = xv.x + hv.x; v[i*4+1] = xv.y + hv.y;
        v[i*4+2] = xv.z + hv.z; v[i*4+3] = xv.w + hv.w;
        s += v[i*4+0] + v[i*4+1] + v[i*4+2] + v[i*4+3];
    }
    #pragma unroll
    for (int o = 16; o > 0; o >>= 1) s += __shfl_xor_sync(0xffffffffu, s, o);
    float mu = s * (1.f / DM);
    float s2 = 0.f;
    #pragma unroll
    for (int i = 0; i < 16; i++) { float d = v[i] - mu; s2 += d * d; }
    #pragma unroll
    for (int o = 16; o > 0; o >>= 1) s2 += __shfl_xor_sync(0xffffffffu, s2, o);
    float inv = rsqrtf(s2 * (1.f / DM) + 1e-5f);

    #pragma unroll
    for (int i = 0; i < 4; i++) {
        int c = i * 128 + lane * 4;
        float o0 = (v[i*4+0] - mu) * inv * g[c + 0] + b[c + 0];
        float o1 = (v[i*4+1] - mu) * inv * g[c + 1] + b[c + 1];
        float o2 = (v[i*4+2] - mu) * inv * g[c + 2] + b[c + 2];
        float o3 = (v[i*4+3] - mu) * inv * g[c + 3] + b[c + 3];
        __half h0, l0, h1, l1, h2, l2, h3, l3;
        f16_split(o0, h0, l0); f16_split(o1, h1, l1);
        f16_split(o2, h2, l2); f16_split(o3, h3, l3);
        size_t idx = (size_t)row * DM + c;
        if (out) *(float4*)(out + idx) = make_float4(o0, o1, o2, o3);
        *(__half2*)(oh + idx)     = __halves2half2(h0, h1);
        *(__half2*)(oh + idx + 2) = __halves2half2(h2, h3);
        *(__half2*)(ol + idx)     = __halves2half2(l0, l1);
        *(__half2*)(ol + idx + 2) = __halves2half2(l2, l3);
    }
}

// ---------------- gumbel argmax + flag ----------------
__device__ __forceinline__ float gumbelf(float u) {
    return -logf(-logf(u + 1e-10f) + 1e-10f);
}

__global__ void gumbel_kernel(const float* __restrict__ u_m, const float* __restrict__ u_k,
                              const float* __restrict__ klog) {
    int r = blockIdx.x * blockDim.x + threadIdx.x;
    if (r >= MTOT) return;
    int s = r % SS;
    float zm0 = g_mlog[r * 2 + 0] + gumbelf(u_m[r * 2 + 0]);
    float zm1 = g_mlog[r * 2 + 1] + gumbelf(u_m[r * 2 + 1]);
    int mhard = (zm1 > zm0) ? 1 : 0;
    int flag = (s == 0) ? 1 : (mhard == 0 ? 1 : 0);
    g_flag[r] = flag;

    float best = -1e30f; int bi = 0;
    #pragma unroll 5
    for (int i = 0; i < NKK; i++) {
        float z = klog[(size_t)r * 128 + i] + gumbelf(u_k[r * NKK + i]);
        if (z > best) { best = z; bi = i; }
    }
    g_kidx[r] = bi;
}

// ---------------- per-batch forward-fill scan: warp ballot/clz ----------------
__global__ void scan_kernel() {
    int w = threadIdx.x >> 5;
    int lane = threadIdx.x & 31;
    if (w >= BB) return;
    int carry = 0;
    for (int t0 = 0; t0 < SS; t0 += 32) {
        int r = w * SS + t0 + lane;
        int f = g_flag[r];
        int k = g_kidx[r];
        unsigned mask = __ballot_sync(0xffffffffu, f);
        unsigned lower = mask & (0xffffffffu >> (31 - lane));
        int src = 31 - __clz(lower);
        int val = __shfl_sync(0xffffffffu, k, src & 31);
        if (lower == 0) val = carry;
        g_fill[r] = val;
        carry = __shfl_sync(0xffffffffu, val, 31);
    }
}

// ---------------- assemble the 4 outputs ----------------
__global__ __launch_bounds__(64)
void output_kernel(float* __restrict__ out, const float* __restrict__ klog) {
    int r = blockIdx.x;
    int tid = threadIdx.x;
    int s = r % SS;

    float m0 = g_mlog[r * 2 + 0], m1 = g_mlog[r * 2 + 1];
    float mx = fmaxf(m0, m1);
    float e0 = expf(m0 - mx), e1 = expf(m1 - mx);
    float inv = 1.f / (e0 + e1);
    float p0 = e0 * inv, p1 = e1 * inv;

    __shared__ float s_max, s_sum;
    if (tid < 32) {
        const float* kl = klog + (size_t)r * 128;
        float v0 = (tid < NKK) ? kl[tid] : -1e30f;
        float v1 = (tid + 32 < NKK) ? kl[tid + 32] : -1e30f;
        float km = fmaxf(v0, v1);
        #pragma unroll
        for (int o = 16; o > 0; o >>= 1)
            km = fmaxf(km, __shfl_xor_sync(0xffffffffu, km, o));
        float e = 0.f;
        if (tid < NKK)      e += expf(v0 - km);
        if (tid + 32 < NKK) e += expf(v1 - km);
        #pragma unroll
        for (int o = 16; o > 0; o >>= 1)
            e += __shfl_xor_sync(0xffffffffu, e, o);
        if (tid == 0) { s_max = km; s_sum = e; }
    }
    __syncthreads();

    int fill = g_fill[r];
    int fill_prev = (s > 0) ? g_fill[r - 1] : -1;

    float* o_sk = out;
    float* o_ms = out + (size_t)MTOT * NKK;
    float* o_kp = out + (size_t)MTOT * NKK + (size_t)MTOT * 2;
    float* o_mp = out + (size_t)MTOT * NKK * 2 + (size_t)MTOT * 2;

    if (tid < NKK) {
        float ksoft = expf(klog[(size_t)r * 128 + tid] - s_max) / s_sum;
        float sk  = (tid == fill)      ? 1.f : 0.f;
        float skl = (tid == fill_prev) ? 1.f : 0.f;
        o_sk[(size_t)r * NKK + tid] = sk;
        o_kp[(size_t)r * NKK + tid] = skl * p1 + ksoft * p0;
    }
    if (tid == 0) {
        float f = (float)g_flag[r];
        o_ms[(size_t)r * 2 + 0] = f;
        o_ms[(size_t)r * 2 + 1] = 1.f - f;
        o_mp[(size_t)r * 2 + 0] = p0;
        o_mp[(size_t)r * 2 + 1] = p1;
    }
}

// ---------------- launcher ----------------
extern "C" void kernel_launch(void* const* d_in, const int* in_sizes, int n_in,
                              void* d_out, int out_size) {
    const float* state_feat = (const float*)d_in[0];
    const float* act_feat   = (const float*)d_in[1];
    const float* goal_feat  = (const float*)d_in[2];
    const float* u_m   = (const float*)d_in[4];
    const float* u_k   = (const float*)d_in[5];
    const float* W_in  = (const float*)d_in[6];
    const float* b_in  = (const float*)d_in[7];
    const float* Wqkv  = (const float*)d_in[8];
    const float* bqkv  = (const float*)d_in[9];
    const float* Wo    = (const float*)d_in[10];
    const float* bo    = (const float*)d_in[11];
    const float* ln1_g = (const float*)d_in[12];
    const float* ln1_b = (const float*)d_in[13];
    const float* W1    = (const float*)d_in[14];
    const float* b1    = (const float*)d_in[15];
    const float* W2    = (const float*)d_in[16];
    const float* b2    = (const float*)d_in[17];
    const float* ln2_g = (const float*)d_in[18];
    const float* ln2_b = (const float*)d_in[19];
    const float* W_out = (const float*)d_in[20];
    const float* b_out = (const float*)d_in[21];
    const float* W_k1  = (const float*)d_in[22];
    const float* b_k1  = (const float*)d_in[23];
    const float* W_sub = (const float*)d_in[24];
    const float* b_sub = (const float*)d_in[25];
    const float* W_term= (const float*)d_in[26];
    const float* b_term= (const float*)d_in[27];

    __half *p_fh, *p_fl, *p_xh, *p_xl, *p_qkvh, *p_qkvl, *p_oh, *p_ol;
    __half *p_ffnh, *p_ffnl, *p_outh, *p_outl, *p_wth, *p_wtl;
    float *p_x, *p_klog, *p_proj, *p_out, *p_bsub, *p_bqkv;
    cudaGetSymbolAddress((void**)&p_fh,   g_fh);
    cudaGetSymbolAddress((void**)&p_fl,   g_fl);
    cudaGetSymbolAddress((void**)&p_x,    g_x);
    cudaGetSymbolAddress((void**)&p_xh,   g_xh);
    cudaGetSymbolAddress((void**)&p_xl,   g_xl);
    cudaGetSymbolAddress((void**)&p_qkvh, g_qkvh);
    cudaGetSymbolAddress((void**)&p_qkvl, g_qkvl);
    cudaGetSymbolAddress((void**)&p_klog, g_klog);
    cudaGetSymbolAddress((void**)&p_oh,   g_oh);
    cudaGetSymbolAddress((void**)&p_ol,   g_ol);
    cudaGetSymbolAddress((void**)&p_proj, g_proj);
    cudaGetSymbolAddress((void**)&p_ffnh, g_ffnh);
    cudaGetSymbolAddress((void**)&p_ffnl, g_ffnl);
    cudaGetSymbolAddress((void**)&p_out,  g_out);
    cudaGetSymbolAddress((void**)&p_outh, g_outh);
    cudaGetSymbolAddress((void**)&p_outl, g_outl);
    cudaGetSymbolAddress((void**)&p_wth,  g_wth);
    cudaGetSymbolAddress((void**)&p_wtl,  g_wtl);
    cudaGetSymbolAddress((void**)&p_bsub, g_bsub);
    cudaGetSymbolAddress((void**)&p_bqkv, g_bqkv);
    __half* p_hidh = p_ffnh;
    __half* p_hidl = p_ffnl;

    cudaFuncSetAttribute(tgemm<false, true,  true >, cudaFuncAttributeMaxDynamicSharedMemorySize, TG_SMEM);
    cudaFuncSetAttribute(tgemm<false, true,  false>, cudaFuncAttributeMaxDynamicSharedMemorySize, TG_SMEM);
    cudaFuncSetAttribute(tgemm<false, false, true >, cudaFuncAttributeMaxDynamicSharedMemorySize, TG_SMEM);
    cudaFuncSetAttribute(tgemm<true,  false, true >, cudaFuncAttributeMaxDynamicSharedMemorySize, TG_SMEM);
    cudaFuncSetAttribute(attn_mma, cudaFuncAttributeMaxDynamicSharedMemorySize, ATT_SMEM_B);

    dim3 tb(32, 8);
    tsplit<<<dim3(512/32, 576/32), tb>>>(W_in, p_wth + OFF_WIN, p_wtl + OFF_WIN, D_IN, DM, DM, 1.f, 0);
    tsplit<<<dim3(1536/32, 512/32), tb>>>(Wqkv, p_wth + OFF_QKV(0), p_wtl + OFF_QKV(0), DM, 3*DM, 3*DM, 0.125f, DM);
    concat_split<<<(MTOT * D_IN + 255) / 256, 256>>>(state_feat, act_feat, goal_feat);
    tgemm<false, true, true><<<dim3(DM/128, MTOT/64), 256, TG_SMEM>>>(
        p_fh, p_fl, p_wth + OFF_WIN, p_wtl + OFF_WIN, b_in, p_x, p_xh, p_xl, DM, D_IN);
    scale_bqkv<<<6, 256>>>(bqkv);

    for (int l = 0; l < NL; l++) {
        if (l > 0) {
            tsplit<<<dim3(1536/32, 512/32), tb>>>(Wqkv + (size_t)l*DM*3*DM, p_wth + OFF_QKV(l), p_wtl + OFF_QKV(l), DM, 3*DM, 3*DM, 0.125f, DM);
            scale_bqkv<<<6, 256>>>(bqkv + (size_t)l*3*DM);
        }
        tgemm<false, false, true><<<dim3(3*DM/128, MTOT/64), 256, TG_SMEM>>>(
            p_xh, p_xl, p_wth + OFF_QKV(l), p_wtl + OFF_QKV(l), p_bqkv,
            nullptr, p_qkvh, p_qkvl, 3*DM, DM);
        attn_mma<<<dim3(SS/64, NH, BB), 256, ATT_SMEM_B>>>(p_qkvh, p_qkvl, p_oh, p_ol);
        tsplit<<<dim3(512/32, 512/32), tb>>>(Wo + (size_t)l*DM*DM, p_wth + OFF_WO(l), p_wtl + OFF_WO(l), DM, DM, DM, 1.f, 0);
        tgemm<false, true, false><<<dim3(DM/128, MTOT/64), 256, TG_SMEM>>>(
            p_oh, p_ol, p_wth + OFF_WO(l), p_wtl + OFF_WO(l), bo + (size_t)l*DM,
            p_proj, nullptr, nullptr, DM, DM);
        ln_kernel<<<MTOT/4, 128>>>(p_x, p_proj, ln1_g + (size_t)l*DM, ln1_b + (size_t)l*DM, p_x, p_xh, p_xl);
        tsplit<<<dim3(2048/32, 512/32), tb>>>(W1 + (size_t)l*DM*DFF, p_wth + OFF_W1(l), p_wtl + OFF_W1(l), DM, DFF, DFF, 1.f, 0);
        tgemm<true, false, true><<<dim3(DFF/128, MTOT/64), 256, TG_SMEM>>>(
            p_xh, p_xl, p_wth + OFF_W1(l), p_wtl + OFF_W1(l), b1 + (size_t)l*DFF,
            nullptr, p_ffnh, p_ffnl, DFF, DM);
        tsplit<<<dim3(512/32, 2048/32), tb>>>(W2 + (size_t)l*DFF*DM, p_wth + OFF_W2(l), p_wtl + OFF_W2(l), DFF, DM, DM, 1.f, 0);
        tgemm<false, true, false><<<dim3(DM/128, MTOT/64), 256, TG_SMEM>>>(
            p_ffnh, p_ffnl, p_wth + OFF_W2(l), p_wtl + OFF_W2(l), b2 + (size_t)l*DM,
            p_proj, nullptr, nullptr, DM, DFF);
        ln_kernel<<<MTOT/4, 128>>>(p_x, p_proj, ln2_g + (size_t)l*DM, ln2_b + (size_t)l*DM,
                                   (l == NL - 1) ? nullptr : p_x, p_xh, p_xl);
    }

    // heads
    tsplit<<<dim3(128/32, 512/32), tb>>>(W_out, p_wth + OFF_WOUT, p_wtl + OFF_WOUT, DM, DHID, DHID, 1.f, 0);
    tsplit<<<dim3(128/32, 128/32), tb>>>(W_k1,  p_wth + OFF_WK1,  p_wtl + OFF_WK1,  DHID, DHID, DHID, 1.f, 0);
    tsplit<<<dim3(128/32, 128/32), tb>>>(W_sub, p_wth + OFF_WSUB, p_wtl + OFF_WSUB, DHID, 128, NKK, 1.f, 0);
    bias_pad<<<1, 128>>>(b_sub, p_bsub, NKK);

    tgemm<false, true, true><<<dim3(DHID/128, MTOT/64), 256, TG_SMEM>>>(
        p_xh, p_xl, p_wth + OFF_WOUT, p_wtl + OFF_WOUT, b_out, p_out, p_outh, p_outl, DHID, DM);
    tgemm<true, false, true><<<dim3(DHID/128, MTOT/64), 256, TG_SMEM>>>(
        p_outh, p_outl, p_wth + OFF_WK1, p_wtl + OFF_WK1, b_k1, nullptr, p_hidh, p_hidl, DHID, DHID);
    tgemm<false, true, false><<<dim3(1, MTOT/64), 256, TG_SMEM>>>(
        p_hidh, p_hidl, p_wth + OFF_WSUB, p_wtl + OFF_WSUB, p_bsub, p_klog, nullptr, nullptr, 128, DHID);
    mlogit_kernel<<<MTOT/4, 128>>>(p_out, W_term, b_term);

    // discrete tail
    gumbel_kernel<<<(MTOT + 255) / 256, 256>>>(u_m, u_k, p_klog);
    scan_kernel<<<1, 512>>>();
    output_kernel<<<MTOT, 64>>>((float*)d_out, p_klog);
}

// round 16
// speedup vs baseline: 1.0173x; 1.0173x over previous
#include <cuda_runtime.h>
#include <cuda_fp16.h>
#include <math.h>
#include <stdint.h>

// ---------------- problem constants ----------------
#define BB 16
#define SS 1024
#define D_IN 576
#define DM 512
#define DFF 2048
#define DHID 128
#define NKK 50
#define NL 3
#define NH 8
#define MTOT (BB*SS)   // 16384

#define WSCALE 256.f
#define WINV   0.00390625f

// ---------------- fp16 split ----------------
__device__ __forceinline__ void f16_split(float v, __half& h, __half& l) {
    h = __float2half_rn(v);
    l = __float2half_rn(v - __half2float(h));
}

// ---------------- scratch ----------------
#define OFF_WIN   0
#define OFF_QKV(l) (368640 + (l) * 983040)
#define OFF_WO(l)  (3317760 + (l) * 327680)
#define OFF_W1(l)  (4300800 + (l) * 1310720)
#define OFF_W2(l)  (8232960 + (l) * 1310720)
#define OFF_WOUT  12165120
#define OFF_WK1   12247040
#define OFF_WSUB  12267520
#define WT_TOTAL  12288000

__device__ __half g_fh  [MTOT * D_IN];
__device__ __half g_fl  [MTOT * D_IN];
__device__ float  g_x   [MTOT * DM];
__device__ __half g_xh  [MTOT * DM];
__device__ __half g_xl  [MTOT * DM];
__device__ __half g_qkvh[MTOT * 3 * DM];
__device__ __half g_qkvl[MTOT * 3 * DM];
__device__ float  g_klog[MTOT * 128];
__device__ __half g_oh  [MTOT * DM];
__device__ __half g_ol  [MTOT * DM];
__device__ float  g_proj[MTOT * DM];
__device__ __half g_ffnh[MTOT * DFF];      // reused late as hid_h
__device__ __half g_ffnl[MTOT * DFF];      // reused late as hid_l
__device__ float  g_out [MTOT * DHID];
__device__ __half g_outh[MTOT * DHID];
__device__ __half g_outl[MTOT * DHID];
__device__ float  g_mlog[MTOT * 2];
__device__ __half g_wth [WT_TOTAL];
__device__ __half g_wtl [WT_TOTAL];
__device__ float  g_bsub[128];
__device__ float  g_bqkv[3 * 3 * DM];      // per-layer pre-scaled QKV bias
__device__ int    g_kidx[MTOT];
__device__ int    g_flag[MTOT];
__device__ int    g_fill[MTOT];

// ---------------- concat + split ----------------
__global__ void concat_split(const float* __restrict__ st, const float* __restrict__ ac,
                             const float* __restrict__ go) {
    int idx = blockIdx.x * blockDim.x + threadIdx.x;
    if (idx >= MTOT * D_IN) return;
    int m = idx / D_IN, c = idx % D_IN;
    float v;
    if (c < 256)      v = st[(size_t)m * 256 + c];
    else if (c < 320) v = ac[(size_t)m * 64 + (c - 256)];
    else              v = go[(size_t)m * 256 + (c - 320)];
    __half h, l;
    f16_split(v, h, l);
    g_fh[idx] = h;
    g_fl[idx] = l;
}

// ---------------- weight transpose + split + fp16 fragment-pack (device core) ----------------
__device__ __forceinline__ void tsplit_block(
    const float* __restrict__ W, __half* __restrict__ Th, __half* __restrict__ Tl,
    int K, int N, int realN, float qscale, int qcut, int bx, int by) {
    __shared__ float t[32][33];
    int k0 = by * 32, n0 = bx * 32;
    int tx = threadIdx.x, ty = threadIdx.y;  // 32x8
    #pragma unroll
    for (int i = ty; i < 32; i += 8) {
        int n = n0 + tx;
        float scl = WSCALE * ((n < qcut) ? qscale : 1.f);
        t[i][tx] = (n < realN) ? W[(size_t)(k0 + i) * realN + n] * scl : 0.f;
    }
    __syncthreads();
    #pragma unroll
    for (int i = ty; i < 32; i += 8) {
        int n = n0 + i, k = k0 + tx;
        float v = t[tx][i];
        __half h, l;
        f16_split(v, h, l);
        int nb = n >> 7, nr = n & 127;
        int kc = k >> 5, ks = (k >> 4) & 1, p = (k & 15) >> 1;
        int tt = p & 3, reg = p >> 2;
        int slot = ((nr >> 6) << 5) + ((nr & 7) << 2) + tt;
        int u32idx = (((nr >> 5) & 1) << 3) + (((nr >> 3) & 3) << 1) + reg;
        size_t off = ((((size_t)(nb * (K >> 5) + kc)) * 2560 + ks * 1280 + slot * 20 + u32idx) << 1) + (k & 1);
        Th[off] = h;
        Tl[off] = l;
    }
}

// ---------------- mega weight-prep: all tsplits in ONE launch ----------------
// ranges: [0,288) W_in | [288,3072) Wqkv x3 | [3072,3840) Wo x3 |
//         [3840,6912) W1 x3 | [6912,9984) W2 x3 | [9984,10048) Wout |
//         [10048,10064) Wk1 | [10064,10080) Wsub
#define TSPLIT_ALL_BLOCKS 10080
__global__ void tsplit_all(const float* __restrict__ W_in, const float* __restrict__ Wqkv,
                           const float* __restrict__ Wo, const float* __restrict__ W1,
                           const float* __restrict__ W2, const float* __restrict__ Wout,
                           const float* __restrict__ Wk1, const float* __restrict__ Wsub) {
    int id = blockIdx.x;
    const float* W; int K, N, realN, gx; float qs = 1.f; int qcut = 0; size_t off;
    int rem;
    if (id < 288) {
        W = W_in; K = D_IN; N = DM; realN = DM; gx = 16; off = OFF_WIN; rem = id;
    } else if (id < 3072) {
        rem = id - 288; int l = rem / 768; rem %= 768;
        W = Wqkv + (size_t)l * DM * 3 * DM; K = DM; N = 3 * DM; realN = 3 * DM;
        gx = 48; off = OFF_QKV(l); qs = 0.125f; qcut = DM;
    } else if (id < 3840) {
        rem = id - 3072; int l = rem / 256; rem %= 256;
        W = Wo + (size_t)l * DM * DM; K = DM; N = DM; realN = DM; gx = 16; off = OFF_WO(l);
    } else if (id < 6912) {
        rem = id - 3840; int l = rem / 1024; rem %= 1024;
        W = W1 + (size_t)l * DM * DFF; K = DM; N = DFF; realN = DFF; gx = 64; off = OFF_W1(l);
    } else if (id < 9984) {
        rem = id - 6912; int l = rem / 1024; rem %= 1024;
        W = W2 + (size_t)l * DFF * DM; K = DFF; N = DM; realN = DM; gx = 16; off = OFF_W2(l);
    } else if (id < 10048) {
        rem = id - 9984;
        W = Wout; K = DM; N = DHID; realN = DHID; gx = 4; off = OFF_WOUT;
    } else if (id < 10064) {
        rem = id - 10048;
        W = Wk1; K = DHID; N = DHID; realN = DHID; gx = 4; off = OFF_WK1;
    } else {
        rem = id - 10064;
        W = Wsub; K = DHID; N = 128; realN = NKK; gx = 4; off = OFF_WSUB;
    }
    tsplit_block(W, g_wth + off, g_wtl + off, K, N, realN, qs, qcut, rem % gx, rem / gx);
}

// ---------------- bias prep: padded b_sub + all pre-scaled QKV biases ----------------
__global__ void bias_prep(const float* __restrict__ b_sub, const float* __restrict__ bqkv) {
    int id = blockIdx.x * 128 + threadIdx.x;
    if (blockIdx.x == 0) {
        g_bsub[id] = (id < NKK) ? b_sub[id] : 0.f;
    } else {
        int idx = id - 128;             // 0 .. 4607
        if (idx < 3 * 3 * DM) {
            int j = idx % (3 * DM);
            g_bqkv[idx] = bqkv[idx] * ((j < DM) ? 0.125f : 1.f);
        }
    }
}

// ---------------- mma.sync fp16 helper ----------------
__device__ __forceinline__ void mma_f16(float* c, const uint32_t* a, const uint32_t* b) {
    asm volatile(
        "mma.sync.aligned.m16n8k16.row.col.f32.f16.f16.f32 "
        "{%0,%1,%2,%3}, {%4,%5,%6,%7}, {%8,%9}, {%0,%1,%2,%3};"
        : "+f"(c[0]), "+f"(c[1]), "+f"(c[2]), "+f"(c[3])
        : "r"(a[0]), "r"(a[1]), "r"(a[2]), "r"(a[3]), "r"(b[0]), "r"(b[1]));
}
__device__ __forceinline__ void cpa16(uint32_t dst, const void* src) {
    asm volatile("cp.async.cg.shared.global [%0], [%1], 16;" :: "r"(dst), "l"(src));
}
__device__ __forceinline__ uint32_t smem_u32(const void* p) {
    uint32_t a;
    asm("{ .reg .u64 t; cvta.to.shared.u64 t, %1; cvt.u32.u64 %0, t; }" : "=r"(a) : "l"(p));
    return a;
}

// ---------------- tensor-pipe fp16x3 GEMM: M=64 tiles, 3 CTAs/SM ----------------
#define TAu 1280
#define TBu 2560
#define STAGE_U 7680
#define TG_SMEM (2 * STAGE_U * 4)   // 61440 bytes -> 3 CTAs/SM

template<bool RELU, bool WRITE_C, bool WRITE_SPLIT>
__global__ __launch_bounds__(256, 3)
void tgemm(const __half* __restrict__ Ah, const __half* __restrict__ Al,
           const __half* __restrict__ Bph, const __half* __restrict__ Bpl,
           const float* __restrict__ bias,
           float* __restrict__ C, __half* __restrict__ Ch, __half* __restrict__ Cl,
           int N, int K) {
    extern __shared__ uint32_t smu[];
    const int tid = threadIdx.x;
    const int wid = tid >> 5, lane = tid & 31;
    const int g = lane >> 2, t = lane & 3;
    const int wm = (wid & 3) * 16;
    const int wcol = wid >> 2;
    const int n0 = blockIdx.x * 128, m0 = blockIdx.y * 64;
    const int NC = K >> 5;
    const uint32_t smb = smem_u32(smu);

    const __half* Agh = Ah + (size_t)m0 * K;
    const __half* Agl = Al + (size_t)m0 * K;
    const size_t bbase = (size_t)blockIdx.x * (K >> 5) * 5120;
    const __half* Bgh = Bph + bbase;
    const __half* Bgl = Bpl + bbase;

    const int rA = tid >> 2, fA = tid & 3;

    auto load_chunk = [&](int c, int s) {
        uint32_t st = smb + s * STAGE_U * 4;
        cpa16(st + (rA * 20 + fA * 4) * 4,        Agh + (size_t)rA * K + c * 32 + fA * 8);
        cpa16(st + (TAu + rA * 20 + fA * 4) * 4,  Agl + (size_t)rA * K + c * 32 + fA * 8);
        const __half* bh = Bgh + (size_t)c * 5120;
        const __half* bl = Bgl + (size_t)c * 5120;
        #pragma unroll
        for (int i = 0; i < 3; i++) {
            int idx = tid + i * 256;
            if (idx < 640) {
                cpa16(st + (2 * TAu + idx * 4) * 4,       bh + idx * 8);
                cpa16(st + (2 * TAu + TBu + idx * 4) * 4, bl + idx * 8);
            }
        }
        asm volatile("cp.async.commit_group;" ::: "memory");
    };

    load_chunk(0, 0);
    if (NC > 1) load_chunk(1, 1);
    else asm volatile("cp.async.commit_group;" ::: "memory");

    float acc[8][4];
    #pragma unroll
    for (int nt = 0; nt < 8; nt++)
        #pragma unroll
        for (int u = 0; u < 4; u++) acc[nt][u] = 0.f;

    for (int c = 0; c < NC; c++) {
        const int buf = c & 1;
        if (c + 1 < NC) asm volatile("cp.async.wait_group 1;" ::: "memory");
        else            asm volatile("cp.async.wait_group 0;" ::: "memory");
        __syncthreads();

        const uint32_t* As_h = smu + buf * STAGE_U;
        const uint32_t* As_l = As_h + TAu;
        const uint32_t* Bs_h = As_h + 2 * TAu;
        const uint32_t* Bs_l = Bs_h + TBu;

        #pragma unroll
        for (int ks = 0; ks < 2; ks++) {
            const int r0 = wm + g;
            const uint32_t* ph = As_h + r0 * 20 + ks * 8 + t;
            const uint32_t* pl = As_l + r0 * 20 + ks * 8 + t;
            uint32_t ah[4] = {ph[0], ph[160], ph[4], ph[164]};
            uint32_t al[4] = {pl[0], pl[160], pl[4], pl[164]};
            const uint32_t* bsh = Bs_h + ks * 1280 + (wcol * 32 + lane) * 20;
            const uint32_t* bsl = Bs_l + ks * 1280 + (wcol * 32 + lane) * 20;
            #pragma unroll
            for (int ntg = 0; ntg < 2; ntg++) {
                uint4 h0 = *(const uint4*)(bsh + ntg * 8);
                uint4 h1 = *(const uint4*)(bsh + ntg * 8 + 4);
                uint4 l0 = *(const uint4*)(bsl + ntg * 8);
                uint4 l1 = *(const uint4*)(bsl + ntg * 8 + 4);
                uint32_t bh[4][2] = {{h0.x, h0.y}, {h0.z, h0.w}, {h1.x, h1.y}, {h1.z, h1.w}};
                uint32_t bl[4][2] = {{l0.x, l0.y}, {l0.z, l0.w}, {l1.x, l1.y}, {l1.z, l1.w}};
                #pragma unroll
                for (int nt = 0; nt < 4; nt++) {
                    mma_f16(acc[ntg * 4 + nt], ah, bh[nt]);
                    mma_f16(acc[ntg * 4 + nt], ah, bl[nt]);
                    mma_f16(acc[ntg * 4 + nt], al, bh[nt]);
                }
            }
        }
        __syncthreads();
        if (c + 2 < NC) load_chunk(c + 2, buf);
    }

    const int row0 = m0 + wm + g;
    #pragma unroll
    for (int nt = 0; nt < 8; nt++) {
        int col = n0 + wcol * 64 + nt * 8 + 2 * t;
        float b0 = bias[col], b1 = bias[col + 1];
        float v00 = acc[nt][0] * WINV + b0, v01 = acc[nt][1] * WINV + b1;
        float v10 = acc[nt][2] * WINV + b0, v11 = acc[nt][3] * WINV + b1;
        if (RELU) {
            v00 = fmaxf(v00, 0.f); v01 = fmaxf(v01, 0.f);
            v10 = fmaxf(v10, 0.f); v11 = fmaxf(v11, 0.f);
        }
        size_t i0 = (size_t)row0 * N + col;
        size_t i1 = (size_t)(row0 + 8) * N + col;
        if (WRITE_C) {
            *(float2*)(C + i0) = make_float2(v00, v01);
            *(float2*)(C + i1) = make_float2(v10, v11);
        }
        if (WRITE_SPLIT) {
            __half h00, l00, h01, l01, h10, l10, h11, l11;
            f16_split(v00, h00, l00); f16_split(v01, h01, l01);
            f16_split(v10, h10, l10); f16_split(v11, h11, l11);
            *(__half2*)(Ch + i0) = __halves2half2(h00, h01);
            *(__half2*)(Cl + i0) = __halves2half2(l00, l01);
            *(__half2*)(Ch + i1) = __halves2half2(h10, h11);
            *(__half2*)(Cl + i1) = __halves2half2(l10, l11);
        }
    }
}

// ---------------- m-logit head: warp-per-row dot (N=2, K=128) ----------------
__global__ __launch_bounds__(128)
void mlogit_kernel(const float* __restrict__ A, const float* __restrict__ W,
                   const float* __restrict__ b) {
    const int wid = threadIdx.x >> 5, lane = threadIdx.x & 31;
    const int r = blockIdx.x * 4 + wid;
    float4 a = *(const float4*)(A + (size_t)r * DHID + lane * 4);
    int k = lane * 4;
    float s0 = a.x * W[k * 2]     + a.y * W[(k + 1) * 2]     + a.z * W[(k + 2) * 2]     + a.w * W[(k + 3) * 2];
    float s1 = a.x * W[k * 2 + 1] + a.y * W[(k + 1) * 2 + 1] + a.z * W[(k + 2) * 2 + 1] + a.w * W[(k + 3) * 2 + 1];
    #pragma unroll
    for (int o = 16; o > 0; o >>= 1) {
        s0 += __shfl_xor_sync(0xffffffffu, s0, o);
        s1 += __shfl_xor_sync(0xffffffffu, s1, o);
    }
    if (lane == 0) {
        g_mlog[r * 2 + 0] = s0 + b[0];
        g_mlog[r * 2 + 1] = s1 + b[1];
    }
}

// ---------------- tensor-core flash attention (fp16x3; pre-split qkv inputs) ----------------
#define APu 36
#define ATT_SMEM_B ((8 * 64 * APu + 7 * 64) * 4)

__global__ __launch_bounds__(256, 2)
void attn_mma(const __half* __restrict__ qkvh, const __half* __restrict__ qkvl,
              __half* __restrict__ oh, __half* __restrict__ ol) {
    extern __shared__ uint32_t smA[];
    uint32_t* Qh  = smA;
    uint32_t* Ql  = Qh  + 64 * APu;
    uint32_t* Kh  = Ql  + 64 * APu;
    uint32_t* Kl  = Kh  + 64 * APu;
    uint32_t* Vth = Kl  + 64 * APu;
    uint32_t* Vtl = Vth + 64 * APu;
    uint32_t* Ph  = Vtl + 64 * APu;
    uint32_t* Pl  = Ph  + 64 * APu;
    float* sm_m     = (float*)(Pl + 64 * APu);
    float* sm_l     = sm_m + 64;
    float* sm_alpha = sm_l + 64;
    float* sm_part  = sm_alpha + 64;
    float* sm_psum  = sm_part + 128;

    const int tid = threadIdx.x;
    const int wid = tid >> 5, lane = tid & 31;
    const int g = lane >> 2, t = lane & 3;
    const int wm = (wid & 3) * 16;
    const int wn = (wid >> 2) * 32;
    const int half_ = wid >> 2;
    const int qt0 = blockIdx.x * 64;
    const int hh = blockIdx.y, bb = blockIdx.z;
    const size_t bbase = (size_t)bb * SS * 1536;

    {
        int r = tid >> 2, dg = tid & 3;
        size_t rowo = bbase + (size_t)(qt0 + r) * 1536 + hh * 64 + dg * 16;
        const uint32_t* qh = (const uint32_t*)(qkvh + rowo);
        const uint32_t* ql = (const uint32_t*)(qkvl + rowo);
        uint32_t* dh = Qh + r * APu + dg * 8;
        uint32_t* dl = Ql + r * APu + dg * 8;
        *(uint4*)(dh)     = *(const uint4*)(qh);
        *(uint4*)(dh + 4) = *(const uint4*)(qh + 4);
        *(uint4*)(dl)     = *(const uint4*)(ql);
        *(uint4*)(dl + 4) = *(const uint4*)(ql + 4);
    }
    if (tid < 64) { sm_m[tid] = -1e30f; sm_l[tid] = 0.f; }

    float o_[4][4];
    #pragma unroll
    for (int nt = 0; nt < 4; nt++)
        #pragma unroll
        for (int u = 0; u < 4; u++) o_[nt][u] = 0.f;

    const int ntiles = qt0 / 64 + 1;
    for (int ti = 0; ti < ntiles; ti++) {
        const int t0 = ti * 64;
        __syncthreads();

        {
            int r = tid >> 2, dg = tid & 3;
            size_t rowo = bbase + (size_t)(t0 + r) * 1536 + hh * 64 + dg * 16;
            const uint32_t* kh = (const uint32_t*)(qkvh + rowo + 512);
            const uint32_t* kl = (const uint32_t*)(qkvl + rowo + 512);
            uint32_t* dh = Kh + r * APu + dg * 8;
            uint32_t* dl = Kl + r * APu + dg * 8;
            *(uint4*)(dh)     = *(const uint4*)(kh);
            *(uint4*)(dh + 4) = *(const uint4*)(kh + 4);
            *(uint4*)(dl)     = *(const uint4*)(kl);
            *(uint4*)(dl + 4) = *(const uint4*)(kl + 4);

            const __half2* vh2 = (const __half2*)(qkvh + rowo + 1024);
            const __half2* vl2 = (const __half2*)(qkvl + rowo + 1024);
            __half* VthH = (__half*)Vth;
            __half* VtlH = (__half*)Vtl;
            int d0 = dg * 16;
            #pragma unroll
            for (int j = 0; j < 8; j++) {
                __half2 hv = vh2[j];
                __half2 lv = vl2[j];
                int d = d0 + 2 * j;
                VthH[(d)     * 2 * APu + r] = __low2half(hv);
                VthH[(d + 1) * 2 * APu + r] = __high2half(hv);
                VtlH[(d)     * 2 * APu + r] = __low2half(lv);
                VtlH[(d + 1) * 2 * APu + r] = __high2half(lv);
            }
        }
        __syncthreads();

        float c0[4][4];
        #pragma unroll
        for (int nt = 0; nt < 4; nt++)
            #pragma unroll
            for (int u = 0; u < 4; u++) c0[nt][u] = 0.f;

        #pragma unroll
        for (int kt = 0; kt < 4; kt++) {
            const int ko = kt * 8;
            const uint32_t* qph = Qh + (wm + g) * APu + ko + t;
            const uint32_t* qpl = Ql + (wm + g) * APu + ko + t;
            uint32_t ahf[4] = {qph[0], qph[8 * APu], qph[4], qph[8 * APu + 4]};
            uint32_t alf[4] = {qpl[0], qpl[8 * APu], qpl[4], qpl[8 * APu + 4]};
            #pragma unroll
            for (int nt = 0; nt < 4; nt++) {
                const uint32_t* kph = Kh + (wn + nt * 8 + g) * APu + ko;
                const uint32_t* kpl = Kl + (wn + nt * 8 + g) * APu + ko;
                uint32_t bhf[2] = {kph[t], kph[t + 4]};
                uint32_t blf[2] = {kpl[t], kpl[t + 4]};
                mma_f16(c0[nt], ahf, bhf);
                mma_f16(c0[nt], ahf, blf);
                mma_f16(c0[nt], alf, bhf);
            }
        }

        if (t0 == qt0) {
            int r0 = qt0 + wm + g, r1 = r0 + 8;
            #pragma unroll
            for (int nt = 0; nt < 4; nt++) {
                int cb = t0 + wn + nt * 8 + 2 * t;
                if (cb     > r0) c0[nt][0] = -1e30f;
                if (cb + 1 > r0) c0[nt][1] = -1e30f;
                if (cb     > r1) c0[nt][2] = -1e30f;
                if (cb + 1 > r1) c0[nt][3] = -1e30f;
            }
        }

        float m0p = -1e30f, m1p = -1e30f;
        #pragma unroll
        for (int nt = 0; nt < 4; nt++) {
            m0p = fmaxf(m0p, fmaxf(c0[nt][0], c0[nt][1]));
            m1p = fmaxf(m1p, fmaxf(c0[nt][2], c0[nt][3]));
        }
        #pragma unroll
        for (int o = 1; o <= 2; o <<= 1) {
            m0p = fmaxf(m0p, __shfl_xor_sync(0xffffffffu, m0p, o));
            m1p = fmaxf(m1p, __shfl_xor_sync(0xffffffffu, m1p, o));
        }
        if (t == 0) {
            sm_part[(wm + g) * 2 + half_] = m0p;
            sm_part[(wm + g + 8) * 2 + half_] = m1p;
        }
        __syncthreads();
        if (tid < 64) {
            float mo = sm_m[tid];
            float mn = fmaxf(mo, fmaxf(sm_part[tid * 2], sm_part[tid * 2 + 1]));
            sm_alpha[tid] = __expf(mo - mn);
            sm_m[tid] = mn;
        }
        __syncthreads();

        {
            float mn0 = sm_m[wm + g], mn1 = sm_m[wm + g + 8];
            float ps0 = 0.f, ps1 = 0.f;
            #pragma unroll
            for (int nt = 0; nt < 4; nt++) {
                int pi = ((wn + nt * 8) >> 1) + t;
                float p00 = __expf(c0[nt][0] - mn0), p01 = __expf(c0[nt][1] - mn0);
                float p10 = __expf(c0[nt][2] - mn1), p11 = __expf(c0[nt][3] - mn1);
                ps0 += p00 + p01; ps1 += p10 + p11;
                __half h00, l00, h01, l01, h10, l10, h11, l11;
                f16_split(p00, h00, l00); f16_split(p01, h01, l01);
                f16_split(p10, h10, l10); f16_split(p11, h11, l11);
                ((__half2*)Ph)[(wm + g) * APu + pi]     = __halves2half2(h00, h01);
                ((__half2*)Pl)[(wm + g) * APu + pi]     = __halves2half2(l00, l01);
                ((__half2*)Ph)[(wm + g + 8) * APu + pi] = __halves2half2(h10, h11);
                ((__half2*)Pl)[(wm + g + 8) * APu + pi] = __halves2half2(l10, l11);
            }
            #pragma unroll
            for (int o = 1; o <= 2; o <<= 1) {
                ps0 += __shfl_xor_sync(0xffffffffu, ps0, o);
                ps1 += __shfl_xor_sync(0xffffffffu, ps1, o);
            }
            if (t == 0) {
                sm_psum[(wm + g) * 2 + half_] = ps0;
                sm_psum[(wm + g + 8) * 2 + half_] = ps1;
            }
        }
        __syncthreads();
        if (tid < 64)
            sm_l[tid] = sm_l[tid] * sm_alpha[tid] + sm_psum[tid * 2] + sm_psum[tid * 2 + 1];

        {
            float al0 = sm_alpha[wm + g], al1 = sm_alpha[wm + g + 8];
            #pragma unroll
            for (int nt = 0; nt < 4; nt++) {
                o_[nt][0] *= al0; o_[nt][1] *= al0;
                o_[nt][2] *= al1; o_[nt][3] *= al1;
            }
            #pragma unroll
            for (int kt = 0; kt < 4; kt++) {
                const int ko = kt * 8;
                const uint32_t* pph = Ph + (wm + g) * APu + ko + t;
                const uint32_t* ppl = Pl + (wm + g) * APu + ko + t;
                uint32_t ahf[4] = {pph[0], pph[8 * APu], pph[4], pph[8 * APu + 4]};
                uint32_t alf[4] = {ppl[0], ppl[8 * APu], ppl[4], ppl[8 * APu + 4]};
                #pragma unroll
                for (int nt = 0; nt < 4; nt++) {
                    const uint32_t* vph = Vth + (wn + nt * 8 + g) * APu + ko;
                    const uint32_t* vpl = Vtl + (wn + nt * 8 + g) * APu + ko;
                    uint32_t bhf[2] = {vph[t], vph[t + 4]};
                    uint32_t blf[2] = {vpl[t], vpl[t + 4]};
                    mma_f16(o_[nt], ahf, bhf);
                    mma_f16(o_[nt], ahf, blf);
                    mma_f16(o_[nt], alf, bhf);
                }
            }
        }
    }

    __syncthreads();
    float il0 = 1.f / sm_l[wm + g], il1 = 1.f / sm_l[wm + g + 8];
    int r0 = bb * SS + qt0 + wm + g;
    #pragma unroll
    for (int nt = 0; nt < 4; nt++) {
        int co = hh * 64 + wn + nt * 8 + 2 * t;
        float v00 = o_[nt][0] * il0, v01 = o_[nt][1] * il0;
        float v10 = o_[nt][2] * il1, v11 = o_[nt][3] * il1;
        __half h00, l00, h01, l01, h10, l10, h11, l11;
        f16_split(v00, h00, l00); f16_split(v01, h01, l01);
        f16_split(v10, h10, l10); f16_split(v11, h11, l11);
        size_t i0 = (size_t)r0 * DM + co;
        size_t i1 = (size_t)(r0 + 8) * DM + co;
        *(__half2*)(oh + i0) = __halves2half2(h00, h01);
        *(__half2*)(ol + i0) = __halves2half2(l00, l01);
        *(__half2*)(oh + i1) = __halves2half2(h10, h11);
        *(__half2*)(ol + i1) = __halves2half2(l10, l11);
    }
}

// ---------------- residual + layernorm: warp-per-row ----------------
__global__ __launch_bounds__(128)
void ln_kernel(const float* __restrict__ x, const float* __restrict__ h,
               const float* __restrict__ g, const float* __restrict__ b,
               float* __restrict__ out, __half* __restrict__ oh, __half* __restrict__ ol) {
    const int wid = threadIdx.x >> 5, lane = threadIdx.x & 31;
    const int row = blockIdx.x * 4 + wid;
    const float* xr = x + (size_t)row * DM;
    const float* hr = h + (size_t)row * DM;

    float v[16];
    float s = 0.f;
    #pragma unroll
    for (int i = 0; i < 4; i++) {
        float4 xv = *(const float4*)(xr + i * 128 + lane * 4);
        float4 hv = *(const float4*)(hr + i * 128 + lane * 4);
        v[i*4+0] = xv.x + hv.x; v[i*4+1] = xv.y + hv.y;
        v[i*4+2] = xv.z + hv.z; v[i*4+3] = xv.w + hv.w;
        s += v[i*4+0] + v[i*4+1] + v[i*4+2] + v[i*4+3];
    }
    #pragma unroll
    for (int o = 16; o > 0; o >>= 1) s += __shfl_xor_sync(0xffffffffu, s, o);
    float mu = s * (1.f / DM);
    float s2 = 0.f;
    #pragma unroll
    for (int i = 0; i < 16; i++) { float d = v[i] - mu; s2 += d * d; }
    #pragma unroll
    for (int o = 16; o > 0; o >>= 1) s2 += __shfl_xor_sync(0xffffffffu, s2, o);
    float inv = rsqrtf(s2 * (1.f / DM) + 1e-5f);

    #pragma unroll
    for (int i = 0; i < 4; i++) {
        int c = i * 128 + lane * 4;
        float o0 = (v[i*4+0] - mu) * inv * g[c + 0] + b[c + 0];
        float o1 = (v[i*4+1] - mu) * inv * g[c + 1] + b[c + 1];
        float o2 = (v[i*4+2] - mu) * inv * g[c + 2] + b[c + 2];
        float o3 = (v[i*4+3] - mu) * inv * g[c + 3] + b[c + 3];
        __half h0, l0, h1, l1, h2, l2, h3, l3;
        f16_split(o0, h0, l0); f16_split(o1, h1, l1);
        f16_split(o2, h2, l2); f16_split(o3, h3, l3);
        size_t idx = (size_t)row * DM + c;
        *(float4*)(out + idx)   = make_float4(o0, o1, o2, o3);
        *(__half2*)(oh + idx)     = __halves2half2(h0, h1);
        *(__half2*)(oh + idx + 2) = __halves2half2(h2, h3);
        *(__half2*)(ol + idx)     = __halves2half2(l0, l1);
        *(__half2*)(ol + idx + 2) = __halves2half2(l2, l3);
    }
}

// ---------------- gumbel argmax + flag ----------------
__device__ __forceinline__ float gumbelf(float u) {
    return -logf(-logf(u + 1e-10f) + 1e-10f);
}

__global__ void gumbel_kernel(const float* __restrict__ u_m, const float* __restrict__ u_k,
                              const float* __restrict__ klog) {
    int r = blockIdx.x * blockDim.x + threadIdx.x;
    if (r >= MTOT) return;
    int s = r % SS;
    float zm0 = g_mlog[r * 2 + 0] + gumbelf(u_m[r * 2 + 0]);
    float zm1 = g_mlog[r * 2 + 1] + gumbelf(u_m[r * 2 + 1]);
    int mhard = (zm1 > zm0) ? 1 : 0;
    int flag = (s == 0) ? 1 : (mhard == 0 ? 1 : 0);
    g_flag[r] = flag;

    float best = -1e30f; int bi = 0;
    #pragma unroll 5
    for (int i = 0; i < NKK; i++) {
        float z = klog[(size_t)r * 128 + i] + gumbelf(u_k[r * NKK + i]);
        if (z > best) { best = z; bi = i; }
    }
    g_kidx[r] = bi;
}

// ---------------- per-batch forward-fill scan: warp ballot/clz ----------------
__global__ void scan_kernel() {
    int w = threadIdx.x >> 5;
    int lane = threadIdx.x & 31;
    if (w >= BB) return;
    int carry = 0;
    for (int t0 = 0; t0 < SS; t0 += 32) {
        int r = w * SS + t0 + lane;
        int f = g_flag[r];
        int k = g_kidx[r];
        unsigned mask = __ballot_sync(0xffffffffu, f);
        unsigned lower = mask & (0xffffffffu >> (31 - lane));
        int src = 31 - __clz(lower);
        int val = __shfl_sync(0xffffffffu, k, src & 31);
        if (lower == 0) val = carry;
        g_fill[r] = val;
        carry = __shfl_sync(0xffffffffu, val, 31);
    }
}

// ---------------- assemble the 4 outputs ----------------
__global__ __launch_bounds__(64)
void output_kernel(float* __restrict__ out, const float* __restrict__ klog) {
    int r = blockIdx.x;
    int tid = threadIdx.x;
    int s = r % SS;

    float m0 = g_mlog[r * 2 + 0], m1 = g_mlog[r * 2 + 1];
    float mx = fmaxf(m0, m1);
    float e0 = expf(m0 - mx), e1 = expf(m1 - mx);
    float inv = 1.f / (e0 + e1);
    float p0 = e0 * inv, p1 = e1 * inv;

    __shared__ float s_max, s_sum;
    if (tid < 32) {
        const float* kl = klog + (size_t)r * 128;
        float v0 = (tid < NKK) ? kl[tid] : -1e30f;
        float v1 = (tid + 32 < NKK) ? kl[tid + 32] : -1e30f;
        float km = fmaxf(v0, v1);
        #pragma unroll
        for (int o = 16; o > 0; o >>= 1)
            km = fmaxf(km, __shfl_xor_sync(0xffffffffu, km, o));
        float e = 0.f;
        if (tid < NKK)      e += expf(v0 - km);
        if (tid + 32 < NKK) e += expf(v1 - km);
        #pragma unroll
        for (int o = 16; o > 0; o >>= 1)
            e += __shfl_xor_sync(0xffffffffu, e, o);
        if (tid == 0) { s_max = km; s_sum = e; }
    }
    __syncthreads();

    int fill = g_fill[r];
    int fill_prev = (s > 0) ? g_fill[r - 1] : -1;

    float* o_sk = out;
    float* o_ms = out + (size_t)MTOT * NKK;
    float* o_kp = out + (size_t)MTOT * NKK + (size_t)MTOT * 2;
    float* o_mp = out + (size_t)MTOT * NKK * 2 + (size_t)MTOT * 2;

    if (tid < NKK) {
        float ksoft = expf(klog[(size_t)r * 128 + tid] - s_max) / s_sum;
        float sk  = (tid == fill)      ? 1.f : 0.f;
        float skl = (tid == fill_prev) ? 1.f : 0.f;
        o_sk[(size_t)r * NKK + tid] = sk;
        o_kp[(size_t)r * NKK + tid] = skl * p1 + ksoft * p0;
    }
    if (tid == 0) {
        float f = (float)g_flag[r];
        o_ms[(size_t)r * 2 + 0] = f;
        o_ms[(size_t)r * 2 + 1] = 1.f - f;
        o_mp[(size_t)r * 2 + 0] = p0;
        o_mp[(size_t)r * 2 + 1] = p1;
    }
}

// ---------------- launcher ----------------
extern "C" void kernel_launch(void* const* d_in, const int* in_sizes, int n_in,
                              void* d_out, int out_size) {
    const float* state_feat = (const float*)d_in[0];
    const float* act_feat   = (const float*)d_in[1];
    const float* goal_feat  = (const float*)d_in[2];
    const float* u_m   = (const float*)d_in[4];
    const float* u_k   = (const float*)d_in[5];
    const float* W_in  = (const float*)d_in[6];
    const float* b_in  = (const float*)d_in[7];
    const float* Wqkv  = (const float*)d_in[8];
    const float* bqkv  = (const float*)d_in[9];
    const float* Wo    = (const float*)d_in[10];
    const float* bo    = (const float*)d_in[11];
    const float* ln1_g = (const float*)d_in[12];
    const float* ln1_b = (const float*)d_in[13];
    const float* W1    = (const float*)d_in[14];
    const float* b1    = (const float*)d_in[15];
    const float* W2    = (const float*)d_in[16];
    const float* b2    = (const float*)d_in[17];
    const float* ln2_g = (const float*)d_in[18];
    const float* ln2_b = (const float*)d_in[19];
    const float* W_out = (const float*)d_in[20];
    const float* b_out = (const float*)d_in[21];
    const float* W_k1  = (const float*)d_in[22];
    const float* b_k1  = (const float*)d_in[23];
    const float* W_sub = (const float*)d_in[24];
    const float* b_sub = (const float*)d_in[25];
    const float* W_term= (const float*)d_in[26];
    const float* b_term= (const float*)d_in[27];

    __half *p_fh, *p_fl, *p_xh, *p_xl, *p_qkvh, *p_qkvl, *p_oh, *p_ol;
    __half *p_ffnh, *p_ffnl, *p_outh, *p_outl, *p_wth, *p_wtl;
    float *p_x, *p_klog, *p_proj, *p_out, *p_bsub, *p_bqkv;
    cudaGetSymbolAddress((void**)&p_fh,   g_fh);
    cudaGetSymbolAddress((void**)&p_fl,   g_fl);
    cudaGetSymbolAddress((void**)&p_x,    g_x);
    cudaGetSymbolAddress((void**)&p_xh,   g_xh);
    cudaGetSymbolAddress((void**)&p_xl,   g_xl);
    cudaGetSymbolAddress((void**)&p_qkvh, g_qkvh);
    cudaGetSymbolAddress((void**)&p_qkvl, g_qkvl);
    cudaGetSymbolAddress((void**)&p_klog, g_klog);
    cudaGetSymbolAddress((void**)&p_oh,   g_oh);
    cudaGetSymbolAddress((void**)&p_ol,   g_ol);
    cudaGetSymbolAddress((void**)&p_proj, g_proj);
    cudaGetSymbolAddress((void**)&p_ffnh, g_ffnh);
    cudaGetSymbolAddress((void**)&p_ffnl, g_ffnl);
    cudaGetSymbolAddress((void**)&p_out,  g_out);
    cudaGetSymbolAddress((void**)&p_outh, g_outh);
    cudaGetSymbolAddress((void**)&p_outl, g_outl);
    cudaGetSymbolAddress((void**)&p_wth,  g_wth);
    cudaGetSymbolAddress((void**)&p_wtl,  g_wtl);
    cudaGetSymbolAddress((void**)&p_bsub, g_bsub);
    cudaGetSymbolAddress((void**)&p_bqkv, g_bqkv);
    __half* p_hidh = p_ffnh;
    __half* p_hidl = p_ffnl;

    cudaFuncSetAttribute(tgemm<false, true,  true >, cudaFuncAttributeMaxDynamicSharedMemorySize, TG_SMEM);
    cudaFuncSetAttribute(tgemm<false, true,  false>, cudaFuncAttributeMaxDynamicSharedMemorySize, TG_SMEM);
    cudaFuncSetAttribute(tgemm<false, false, true >, cudaFuncAttributeMaxDynamicSharedMemorySize, TG_SMEM);
    cudaFuncSetAttribute(tgemm<true,  false, true >, cudaFuncAttributeMaxDynamicSharedMemorySize, TG_SMEM);
    cudaFuncSetAttribute(attn_mma, cudaFuncAttributeMaxDynamicSharedMemorySize, ATT_SMEM_B);

    dim3 tb(32, 8);
    // ---- all prep in 3 launches ----
    tsplit_all<<<TSPLIT_ALL_BLOCKS, tb>>>(W_in, Wqkv, Wo, W1, W2, W_out, W_k1, W_sub);
    bias_prep<<<37, 128>>>(b_sub, bqkv);
    concat_split<<<(MTOT * D_IN + 255) / 256, 256>>>(state_feat, act_feat, goal_feat);

    // ---- compute chain ----
    tgemm<false, true, true><<<dim3(DM/128, MTOT/64), 256, TG_SMEM>>>(
        p_fh, p_fl, p_wth + OFF_WIN, p_wtl + OFF_WIN, b_in, p_x, p_xh, p_xl, DM, D_IN);

    for (int l = 0; l < NL; l++) {
        tgemm<false, false, true><<<dim3(3*DM/128, MTOT/64), 256, TG_SMEM>>>(
            p_xh, p_xl, p_wth + OFF_QKV(l), p_wtl + OFF_QKV(l), p_bqkv + l * 3 * DM,
            nullptr, p_qkvh, p_qkvl, 3*DM, DM);
        attn_mma<<<dim3(SS/64, NH, BB), 256, ATT_SMEM_B>>>(p_qkvh, p_qkvl, p_oh, p_ol);
        tgemm<false, true, false><<<dim3(DM/128, MTOT/64), 256, TG_SMEM>>>(
            p_oh, p_ol, p_wth + OFF_WO(l), p_wtl + OFF_WO(l), bo + (size_t)l*DM,
            p_proj, nullptr, nullptr, DM, DM);
        ln_kernel<<<MTOT/4, 128>>>(p_x, p_proj, ln1_g + (size_t)l*DM, ln1_b + (size_t)l*DM, p_x, p_xh, p_xl);
        tgemm<true, false, true><<<dim3(DFF/128, MTOT/64), 256, TG_SMEM>>>(
            p_xh, p_xl, p_wth + OFF_W1(l), p_wtl + OFF_W1(l), b1 + (size_t)l*DFF,
            nullptr, p_ffnh, p_ffnl, DFF, DM);
        tgemm<false, true, false><<<dim3(DM/128, MTOT/64), 256, TG_SMEM>>>(
            p_ffnh, p_ffnl, p_wth + OFF_W2(l), p_wtl + OFF_W2(l), b2 + (size_t)l*DM,
            p_proj, nullptr, nullptr, DM, DFF);
        ln_kernel<<<MTOT/4, 128>>>(p_x, p_proj, ln2_g + (size_t)l*DM, ln2_b + (size_t)l*DM, p_x, p_xh, p_xl);
    }

    // heads
    tgemm<false, true, true><<<dim3(DHID/128, MTOT/64), 256, TG_SMEM>>>(
        p_xh, p_xl, p_wth + OFF_WOUT, p_wtl + OFF_WOUT, b_out, p_out, p_outh, p_outl, DHID, DM);
    tgemm<true, false, true><<<dim3(DHID/128, MTOT/64), 256, TG_SMEM>>>(
        p_outh, p_outl, p_wth + OFF_WK1, p_wtl + OFF_WK1, b_k1, nullptr, p_hidh, p_hidl, DHID, DHID);
    tgemm<false, true, false><<<dim3(1, MTOT/64), 256, TG_SMEM>>>(
        p_hidh, p_hidl, p_wth + OFF_WSUB, p_wtl + OFF_WSUB, p_bsub, p_klog, nullptr, nullptr, 128, DHID);
    mlogit_kernel<<<MTOT/4, 128>>>(p_out, W_term, b_term);

    // discrete tail
    gumbel_kernel<<<(MTOT + 255) / 256, 256>>>(u_m, u_k, p_klog);
    scan_kernel<<<1, 512>>>();
    output_kernel<<<MTOT, 64>>>((float*)d_out, p_klog);
}